// round 11
// baseline (speedup 1.0000x reference)
#include <cuda_runtime.h>
#include <math.h>
#include <stdint.h>

#define HH   256
#define NN   64
#define NP   32      // n-pairs
#define NG   16      // packed pair-groups (2 pairs per f32x2)
#define LL   2048
#define FF   1025
#define MM   1024
#define TPB  256

// ---- f32x2 packed helpers (Blackwell) ----
__device__ __forceinline__ uint64_t pk2(float lo, float hi) {
    uint64_t r; asm("mov.b64 %0,{%1,%2};" : "=l"(r) : "f"(lo), "f"(hi)); return r;
}
__device__ __forceinline__ void up2(uint64_t v, float& lo, float& hi) {
    asm("mov.b64 {%0,%1},%2;" : "=f"(lo), "=f"(hi) : "l"(v));
}
__device__ __forceinline__ uint64_t add2(uint64_t a, uint64_t b) {
    uint64_t d; asm("add.rn.f32x2 %0,%1,%2;" : "=l"(d) : "l"(a), "l"(b)); return d;
}
__device__ __forceinline__ uint64_t mul2(uint64_t a, uint64_t b) {
    uint64_t d; asm("mul.rn.f32x2 %0,%1,%2;" : "=l"(d) : "l"(a), "l"(b)); return d;
}
__device__ __forceinline__ uint64_t fma2(uint64_t a, uint64_t b, uint64_t c) {
    uint64_t d; asm("fma.rn.f32x2 %0,%1,%2,%3;" : "=l"(d) : "l"(a), "l"(b), "l"(c)); return d;
}
__device__ __forceinline__ uint64_t rcp2(uint64_t v) {
    float lo, hi; up2(v, lo, hi);
    float a, b;
    asm("rcp.approx.f32 %0,%1;" : "=f"(a) : "f"(lo));
    asm("rcp.approx.f32 %0,%1;" : "=f"(b) : "f"(hi));
    return pk2(a, b);
}
__device__ __forceinline__ float lanesum(uint64_t v) {
    float lo, hi; up2(v, lo, hi); return lo + hi;
}

// complex helpers on float2
__device__ __forceinline__ float2 cadd(float2 a, float2 b) { return make_float2(a.x + b.x, a.y + b.y); }
__device__ __forceinline__ float2 csub(float2 a, float2 b) { return make_float2(a.x - b.x, a.y - b.y); }
__device__ __forceinline__ float2 cmul(float2 a, float2 w) {
    return make_float2(a.x * w.x - a.y * w.y, a.x * w.y + a.y * w.x);
}

// Woodbury + bilinear gain epilogue for one frequency -> X in smem
__device__ __forceinline__ void woodbury(float A00r, float A00i, float A01r, float A01i,
                                         float A10r, float A10i, float A11r, float A11i,
                                         float dt, float gi, int f,
                                         float* __restrict__ Xr, float* __restrict__ Xi) {
    float r00r = dt * A00r, r00i = dt * A00i;
    float r01r = dt * A01r, r01i = dt * A01i;
    float r10r = dt * A10r, r10i = dt * A10i;
    float r11r = dt * A11r, r11i = dt * A11i;
    float numr = r01r * r10r - r01i * r10i;
    float numi = r01r * r10i + r01i * r10r;
    float denr = 1.0f + r11r;
    float deni = r11i;
    float dd   = denr * denr + deni * deni;
    float dinv; asm("rcp.approx.f32 %0,%1;" : "=f"(dinv) : "f"(dd));
    float qr = (numr * denr + numi * deni) * dinv;
    float qi = (numi * denr - numr * deni) * dinv;
    float xr = r00r - qr;
    float xi = r00i - qi;
    Xr[f] = xr - xi * gi;      // * (1 + i*gi), gi = tan(pi f / L)
    Xi[f] = xr * gi + xi;
}

// ---------------------------------------------------------------------------
// Fused kernel, one block per h, 256 threads.
// Phase 1: Cauchy via COMMON-DENOMINATOR pole pairs:
//   v0/(z-w0)+v1/(z-w1) = (N1 z + N0)/(z^2 - S z + P), z = i*y purely imag.
//   Per-pair constants precomputed in smem; f32x2 lanes = (pair, pair+1).
//   Each thread owns 4 freqs. 30 packed FMA + 2 MUFU per (freq, 4 n).
// Phase 2: irfft(L=2048) via 1024-pt inverse FFT, radix-4 composed stages.
// ---------------------------------------------------------------------------
__global__ __launch_bounds__(TPB)
void fused_kernel(const float* __restrict__ Cin, const float* __restrict__ Bin,
                  const float* __restrict__ Pin, const float* __restrict__ Win,
                  const float* __restrict__ logdt, float* __restrict__ out) {
    // raw per-n values (setup scratch)
    __shared__ __align__(16) float raw[9][NN];   // 0 wr,1 wi,2 v00r,3 v00i,4 v01r,5 v01i,6 v10r,7 v10i,8 v11r
    // per-pair constants:
    // 0 S_i, 1 -S_r, 2 P_r, 3 P_i,
    // 4..7   A00: N0r, N0i, N1r, -N1i
    // 8..11  A01: N0r, N0i, N1r, -N1i
    // 12..15 A10: N0r, N0i, N1r, -N1i
    // 16..18 A11: N0r, N0i, N1 (real)
    __shared__ __align__(16) float pc[19][NP];
    __shared__ float2 tw[MM / 2];                // e^{+2*pi*i*t/1024}
    __shared__ float Xr[FF + 3], Xi[FF + 3];
    __shared__ float2 Zc[MM];

    const int h   = blockIdx.x;
    const int tid = threadIdx.x;
    const float dt = expf(logdt[h]);

    // twiddle table: 2 entries per thread
#pragma unroll
    for (int j = 0; j < 2; j++) {
        int t = tid + 256 * j;
        float s, c;
        sincospif((float)t * (1.0f / 512.0f), &s, &c);
        tw[t] = make_float2(c, s);
    }

    if (tid < NN) {
        const int base = h * (NN * 2) + tid * 2;
        float cr = Cin[base], ci = Cin[base + 1];
        float br = Bin[base], bi = Bin[base + 1];
        float pr = Pin[base], pi = Pin[base + 1];
        float wr = Win[base], wi = Win[base + 1];
        raw[0][tid] = wr * dt;             // w_dt
        raw[1][tid] = wi * dt;
        raw[2][tid] = br * cr - bi * ci;   // v00 = B*C
        raw[3][tid] = br * ci + bi * cr;
        raw[4][tid] = br * pr + bi * pi;   // v01 = B*conj(P)
        raw[5][tid] = bi * pr - br * pi;
        raw[6][tid] = pr * cr - pi * ci;   // v10 = P*C
        raw[7][tid] = pr * ci + pi * cr;
        raw[8][tid] = pr * pr + pi * pi;   // v11 = |P|^2 (real)
    }
    __syncthreads();

    if (tid < NP) {
        const int n0 = 2 * tid, n1 = 2 * tid + 1;
        float wr0 = raw[0][n0], wi0 = raw[1][n0];
        float wr1 = raw[0][n1], wi1 = raw[1][n1];
        pc[0][tid] = wi0 + wi1;                      //  S_i
        pc[1][tid] = -(wr0 + wr1);                   // -S_r
        pc[2][tid] = wr0 * wr1 - wi0 * wi1;          //  P_r
        pc[3][tid] = wr0 * wi1 + wi0 * wr1;          //  P_i
#pragma unroll
        for (int k = 0; k < 3; k++) {
            float ar0 = raw[2 + 2 * k][n0], ai0 = raw[3 + 2 * k][n0];
            float ar1 = raw[2 + 2 * k][n1], ai1 = raw[3 + 2 * k][n1];
            // N0 = -(a0*w1 + a1*w0), N1 = a0 + a1
            pc[4 + 4 * k][tid] = -(ar0 * wr1 - ai0 * wi1 + ar1 * wr0 - ai1 * wi0);
            pc[5 + 4 * k][tid] = -(ar0 * wi1 + ai0 * wr1 + ar1 * wi0 + ai1 * wr0);
            pc[6 + 4 * k][tid] = ar0 + ar1;
            pc[7 + 4 * k][tid] = -(ai0 + ai1);
        }
        {   // A11: a real
            float a0 = raw[8][n0], a1 = raw[8][n1];
            pc[16][tid] = -(a0 * wr1 + a1 * wr0);    // N0r
            pc[17][tid] = -(a0 * wi1 + a1 * wi0);    // N0i
            pc[18][tid] = a0 + a1;                   // N1 (real)
        }
    }
    __syncthreads();

    // per-freq: y = 2*tan(pi f / L) (z = i*y), negy2 = -y^2, lane-duplicated
    float zis[4];
    uint64_t yk[4], ny2[4];
#pragma unroll
    for (int j = 0; j < 4; j++) {
        int f = tid + 256 * j;
        float s, c;
        sincospif((float)f * (1.0f / LL), &s, &c);
        float y = 2.0f * __fdividef(s, c);
        zis[j] = y;
        yk[j]  = pk2(y, y);
        ny2[j] = pk2(-y * y, -y * y);
    }

    uint64_t a00r[4], a00i[4], a01r[4], a01i[4];
    uint64_t a10r[4], a10i[4], a11r[4], a11i[4];
#pragma unroll
    for (int j = 0; j < 4; j++) {
        a00r[j] = a00i[j] = a01r[j] = a01i[j] = 0;
        a10r[j] = a10i[j] = a11r[j] = a11i[j] = 0;
    }

    const uint64_t* q0  = (const uint64_t*)&pc[0][0];
    const uint64_t* q1  = (const uint64_t*)&pc[1][0];
    const uint64_t* q2  = (const uint64_t*)&pc[2][0];
    const uint64_t* q3  = (const uint64_t*)&pc[3][0];
    const uint64_t* q4  = (const uint64_t*)&pc[4][0];
    const uint64_t* q5  = (const uint64_t*)&pc[5][0];
    const uint64_t* q6  = (const uint64_t*)&pc[6][0];
    const uint64_t* q7  = (const uint64_t*)&pc[7][0];
    const uint64_t* q8  = (const uint64_t*)&pc[8][0];
    const uint64_t* q9  = (const uint64_t*)&pc[9][0];
    const uint64_t* q10 = (const uint64_t*)&pc[10][0];
    const uint64_t* q11 = (const uint64_t*)&pc[11][0];
    const uint64_t* q12 = (const uint64_t*)&pc[12][0];
    const uint64_t* q13 = (const uint64_t*)&pc[13][0];
    const uint64_t* q14 = (const uint64_t*)&pc[14][0];
    const uint64_t* q15 = (const uint64_t*)&pc[15][0];
    const uint64_t* q16 = (const uint64_t*)&pc[16][0];
    const uint64_t* q17 = (const uint64_t*)&pc[17][0];
    const uint64_t* q18 = (const uint64_t*)&pc[18][0];

#pragma unroll 2
    for (int g = 0; g < NG; g++) {         // packed pair-group (2 pairs/lane)
        uint64_t Si  = q0[g], nSr = q1[g], Pr = q2[g], Pi = q3[g];
#pragma unroll
        for (int j = 0; j < 4; j++) {
            // D(iy) = -y^2 + i y*(-S) + P ->
            //   D_r = -y^2 + y*S_i + P_r,  D_i = -y*S_r + P_i
            uint64_t t   = add2(ny2[j], Pr);
            uint64_t Dr  = fma2(yk[j], Si,  t);
            uint64_t Di  = fma2(yk[j], nSr, Pi);
            uint64_t den = fma2(Dr, Dr, mul2(Di, Di));
            uint64_t inv = rcp2(den);
            uint64_t sr  = mul2(Dr, inv);                    //  Re 1/D
            uint64_t msi = mul2(Di, inv);                    // -Im 1/D
            uint64_t si  = msi ^ 0x8000000080000000ULL;      //  Im 1/D (ALU)
            // kind 00
            {
                uint64_t Nr = fma2(yk[j], q7[g], q4[g]);     // N0r - y*N1i
                uint64_t Ni = fma2(yk[j], q6[g], q5[g]);     // N0i + y*N1r
                a00r[j] = fma2(Nr, sr, a00r[j]); a00r[j] = fma2(Ni, msi, a00r[j]);
                a00i[j] = fma2(Nr, si, a00i[j]); a00i[j] = fma2(Ni, sr,  a00i[j]);
            }
            // kind 01
            {
                uint64_t Nr = fma2(yk[j], q11[g], q8[g]);
                uint64_t Ni = fma2(yk[j], q10[g], q9[g]);
                a01r[j] = fma2(Nr, sr, a01r[j]); a01r[j] = fma2(Ni, msi, a01r[j]);
                a01i[j] = fma2(Nr, si, a01i[j]); a01i[j] = fma2(Ni, sr,  a01i[j]);
            }
            // kind 10
            {
                uint64_t Nr = fma2(yk[j], q15[g], q12[g]);
                uint64_t Ni = fma2(yk[j], q14[g], q13[g]);
                a10r[j] = fma2(Nr, sr, a10r[j]); a10r[j] = fma2(Ni, msi, a10r[j]);
                a10i[j] = fma2(Nr, si, a10i[j]); a10i[j] = fma2(Ni, sr,  a10i[j]);
            }
            // kind 11 (N1 real: N_r = N0r, N_i = N0i + y*N1)
            {
                uint64_t Nr = q16[g];
                uint64_t Ni = fma2(yk[j], q18[g], q17[g]);
                a11r[j] = fma2(Nr, sr, a11r[j]); a11r[j] = fma2(Ni, msi, a11r[j]);
                a11i[j] = fma2(Nr, si, a11i[j]); a11i[j] = fma2(Ni, sr,  a11i[j]);
            }
        }
    }

    // Epilogue: lane-sum (over pair halves), Woodbury, gain, write X to smem
#pragma unroll
    for (int j = 0; j < 4; j++) {
        int f = tid + 256 * j;
        woodbury(lanesum(a00r[j]), lanesum(a00i[j]),
                 lanesum(a01r[j]), lanesum(a01i[j]),
                 lanesum(a10r[j]), lanesum(a10i[j]),
                 lanesum(a11r[j]), lanesum(a11i[j]),
                 dt, 0.5f * zis[j], f, Xr, Xi);
    }

    // Nyquist bin f = L/2 (removable singularity): limit = 0.5*dt*sum_n v00r
    if (tid == 0) {
        float sr = 0.f;
        for (int p = 0; p < NP; p++) sr += pc[6][p];   // sum of pair N1r(00) = sum v00r
        Xr[MM] = 0.5f * dt * sr;
        Xi[MM] = 0.f;
    }
    __syncthreads();

    // ---- Phase 2: irfft via 1024-pt complex inverse FFT ----
    const float scl = 1.0f / 2048.0f;
#pragma unroll
    for (int j = 0; j < 4; j++) {
        int k = tid + 256 * j;
        float Xkx = Xr[k],      Xky = Xi[k];
        float Xmx = Xr[MM - k], Xmy = Xi[MM - k];
        if (k == 0) { Xky = 0.f; Xmy = 0.f; }   // drop imag of DC & Nyquist
        float er  = (Xkx + Xmx) * scl;
        float ei  = (Xky - Xmy) * scl;
        float pr  = (Xkx - Xmx) * scl;
        float pi_ = (Xky + Xmy) * scl;
        float s, c;
        sincospif((float)k * (1.0f / MM), &s, &c);  // e^{+i*pi*k/1024}
        float Or = pr * c - pi_ * s;
        float Oi = pr * s + pi_ * c;
        Zc[k] = make_float2(er - Oi, ei + Or);      // Z = E + i*O
    }
    __syncthreads();

    // 10 radix-2 DIF stages executed as 5 fused double-stages.
#pragma unroll
    for (int q = 256; q >= 1; q >>= 2) {
        const int m = tid & (q - 1);
        const int g = ((tid - m) << 2) + m;
        const int t1 = m * (256 / q);

        float2 a = Zc[g], b = Zc[g + q], c = Zc[g + 2 * q], d = Zc[g + 3 * q];

        float2 w1 = tw[t1];
        float2 w2 = tw[t1 + 256];
        float2 t0v = cadd(a, c);
        float2 t1v = cmul(csub(a, c), w1);
        float2 t2v = cadd(b, d);
        float2 t3v = cmul(csub(b, d), w2);

        float2 w3 = tw[m * (512 / q)];
        Zc[g]         = cadd(t0v, t2v);
        Zc[g + q]     = cmul(csub(t0v, t2v), w3);
        Zc[g + 2 * q] = cadd(t1v, t3v);
        Zc[g + 3 * q] = cmul(csub(t1v, t3v), w3);
        __syncthreads();
    }

    float2* out2 = reinterpret_cast<float2*>(out + h * LL);
#pragma unroll
    for (int j = 0; j < 4; j++) {
        int p = tid + 256 * j;
        int n = __brev((unsigned)p) >> 22;   // 10-bit reverse
        out2[n] = Zc[p];
    }
}

extern "C" void kernel_launch(void* const* d_in, const int* in_sizes, int n_in,
                              void* d_out, int out_size) {
    (void)in_sizes; (void)n_in; (void)out_size;
    const float* C  = (const float*)d_in[0];
    const float* B  = (const float*)d_in[1];
    const float* P  = (const float*)d_in[2];
    const float* W  = (const float*)d_in[3];
    const float* ld = (const float*)d_in[4];
    fused_kernel<<<HH, TPB>>>(C, B, P, W, ld, (float*)d_out);
}

// round 12
// speedup vs baseline: 1.4458x; 1.4458x over previous
#include <cuda_runtime.h>
#include <math.h>
#include <stdint.h>

#define HH   256
#define NN   64
#define NP   32      // n-pairs
#define NG   16      // packed pair-groups (2 pairs per f32x2)
#define LL   2048
#define FF   1025
#define MM   1024
#define TPB  256

// ---- f32x2 packed helpers (Blackwell) ----
__device__ __forceinline__ uint64_t pk2(float lo, float hi) {
    uint64_t r; asm("mov.b64 %0,{%1,%2};" : "=l"(r) : "f"(lo), "f"(hi)); return r;
}
__device__ __forceinline__ void up2(uint64_t v, float& lo, float& hi) {
    asm("mov.b64 {%0,%1},%2;" : "=f"(lo), "=f"(hi) : "l"(v));
}
__device__ __forceinline__ uint64_t add2(uint64_t a, uint64_t b) {
    uint64_t d; asm("add.rn.f32x2 %0,%1,%2;" : "=l"(d) : "l"(a), "l"(b)); return d;
}
__device__ __forceinline__ uint64_t mul2(uint64_t a, uint64_t b) {
    uint64_t d; asm("mul.rn.f32x2 %0,%1,%2;" : "=l"(d) : "l"(a), "l"(b)); return d;
}
__device__ __forceinline__ uint64_t fma2(uint64_t a, uint64_t b, uint64_t c) {
    uint64_t d; asm("fma.rn.f32x2 %0,%1,%2,%3;" : "=l"(d) : "l"(a), "l"(b), "l"(c)); return d;
}
__device__ __forceinline__ uint64_t rcp2(uint64_t v) {
    float lo, hi; up2(v, lo, hi);
    float a, b;
    asm("rcp.approx.f32 %0,%1;" : "=f"(a) : "f"(lo));
    asm("rcp.approx.f32 %0,%1;" : "=f"(b) : "f"(hi));
    return pk2(a, b);
}
__device__ __forceinline__ float lanesum(uint64_t v) {
    float lo, hi; up2(v, lo, hi); return lo + hi;
}

// complex helpers on float2
__device__ __forceinline__ float2 cadd(float2 a, float2 b) { return make_float2(a.x + b.x, a.y + b.y); }
__device__ __forceinline__ float2 csub(float2 a, float2 b) { return make_float2(a.x - b.x, a.y - b.y); }
__device__ __forceinline__ float2 cmul(float2 a, float2 w) {
    return make_float2(a.x * w.x - a.y * w.y, a.x * w.y + a.y * w.x);
}

// Woodbury + bilinear gain epilogue for one frequency -> X in smem
__device__ __forceinline__ void woodbury(float A00r, float A00i, float A01r, float A01i,
                                         float A10r, float A10i, float A11r, float A11i,
                                         float dt, float gi, int f,
                                         float* __restrict__ Xr, float* __restrict__ Xi) {
    float r00r = dt * A00r, r00i = dt * A00i;
    float r01r = dt * A01r, r01i = dt * A01i;
    float r10r = dt * A10r, r10i = dt * A10i;
    float r11r = dt * A11r, r11i = dt * A11i;
    float numr = r01r * r10r - r01i * r10i;
    float numi = r01r * r10i + r01i * r10r;
    float denr = 1.0f + r11r;
    float deni = r11i;
    float dd   = denr * denr + deni * deni;
    float dinv; asm("rcp.approx.f32 %0,%1;" : "=f"(dinv) : "f"(dd));
    float qr = (numr * denr + numi * deni) * dinv;
    float qi = (numi * denr - numr * deni) * dinv;
    float xr = r00r - qr;
    float xi = r00i - qi;
    Xr[f] = xr - xi * gi;      // * (1 + i*gi), gi = tan(pi f / L)
    Xi[f] = xr * gi + xi;
}

// ---------------------------------------------------------------------------
// Fused kernel, one block per h, 256 threads, 2 blocks/SM (single wave).
// Phase 1: Cauchy via common-denominator pole pairs, TWO PASSES of 2 freqs
//   each (accumulator registers halved vs R11 so residency stays at 2/SM).
// Phase 2: irfft(L=2048) via 1024-pt inverse FFT, radix-4 composed stages.
// ---------------------------------------------------------------------------
__global__ __launch_bounds__(TPB, 2)
void fused_kernel(const float* __restrict__ Cin, const float* __restrict__ Bin,
                  const float* __restrict__ Pin, const float* __restrict__ Win,
                  const float* __restrict__ logdt, float* __restrict__ out) {
    // raw per-n values (setup scratch)
    __shared__ __align__(16) float raw[9][NN];   // 0 wr,1 wi,2 v00r,3 v00i,4 v01r,5 v01i,6 v10r,7 v10i,8 v11r
    // per-pair constants:
    // 0 S_i, 1 -S_r, 2 P_r, 3 P_i,
    // 4..7   A00: N0r, N0i, N1r, -N1i
    // 8..11  A01: N0r, N0i, N1r, -N1i
    // 12..15 A10: N0r, N0i, N1r, -N1i
    // 16..18 A11: N0r, N0i, N1 (real)
    __shared__ __align__(16) float pc[19][NP];
    __shared__ float2 tw[MM / 2];                // e^{+2*pi*i*t/1024}
    __shared__ float Xr[FF + 3], Xi[FF + 3];
    __shared__ float2 Zc[MM];

    const int h   = blockIdx.x;
    const int tid = threadIdx.x;
    const float dt = expf(logdt[h]);

    // twiddle table: 2 entries per thread
#pragma unroll
    for (int j = 0; j < 2; j++) {
        int t = tid + 256 * j;
        float s, c;
        sincospif((float)t * (1.0f / 512.0f), &s, &c);
        tw[t] = make_float2(c, s);
    }

    if (tid < NN) {
        const int base = h * (NN * 2) + tid * 2;
        float cr = Cin[base], ci = Cin[base + 1];
        float br = Bin[base], bi = Bin[base + 1];
        float pr = Pin[base], pi = Pin[base + 1];
        float wr = Win[base], wi = Win[base + 1];
        raw[0][tid] = wr * dt;             // w_dt
        raw[1][tid] = wi * dt;
        raw[2][tid] = br * cr - bi * ci;   // v00 = B*C
        raw[3][tid] = br * ci + bi * cr;
        raw[4][tid] = br * pr + bi * pi;   // v01 = B*conj(P)
        raw[5][tid] = bi * pr - br * pi;
        raw[6][tid] = pr * cr - pi * ci;   // v10 = P*C
        raw[7][tid] = pr * ci + pi * cr;
        raw[8][tid] = pr * pr + pi * pi;   // v11 = |P|^2 (real)
    }
    __syncthreads();

    if (tid < NP) {
        const int n0 = 2 * tid, n1 = 2 * tid + 1;
        float wr0 = raw[0][n0], wi0 = raw[1][n0];
        float wr1 = raw[0][n1], wi1 = raw[1][n1];
        pc[0][tid] = wi0 + wi1;                      //  S_i
        pc[1][tid] = -(wr0 + wr1);                   // -S_r
        pc[2][tid] = wr0 * wr1 - wi0 * wi1;          //  P_r
        pc[3][tid] = wr0 * wi1 + wi0 * wr1;          //  P_i
#pragma unroll
        for (int k = 0; k < 3; k++) {
            float ar0 = raw[2 + 2 * k][n0], ai0 = raw[3 + 2 * k][n0];
            float ar1 = raw[2 + 2 * k][n1], ai1 = raw[3 + 2 * k][n1];
            // N0 = -(a0*w1 + a1*w0), N1 = a0 + a1
            pc[4 + 4 * k][tid] = -(ar0 * wr1 - ai0 * wi1 + ar1 * wr0 - ai1 * wi0);
            pc[5 + 4 * k][tid] = -(ar0 * wi1 + ai0 * wr1 + ar1 * wi0 + ai1 * wr0);
            pc[6 + 4 * k][tid] = ar0 + ar1;
            pc[7 + 4 * k][tid] = -(ai0 + ai1);
        }
        {   // A11: a real
            float a0 = raw[8][n0], a1 = raw[8][n1];
            pc[16][tid] = -(a0 * wr1 + a1 * wr0);    // N0r
            pc[17][tid] = -(a0 * wi1 + a1 * wi0);    // N0i
            pc[18][tid] = a0 + a1;                   // N1 (real)
        }
    }
    __syncthreads();

    const uint64_t* q0  = (const uint64_t*)&pc[0][0];
    const uint64_t* q1  = (const uint64_t*)&pc[1][0];
    const uint64_t* q2  = (const uint64_t*)&pc[2][0];
    const uint64_t* q3  = (const uint64_t*)&pc[3][0];
    const uint64_t* q4  = (const uint64_t*)&pc[4][0];
    const uint64_t* q5  = (const uint64_t*)&pc[5][0];
    const uint64_t* q6  = (const uint64_t*)&pc[6][0];
    const uint64_t* q7  = (const uint64_t*)&pc[7][0];
    const uint64_t* q8  = (const uint64_t*)&pc[8][0];
    const uint64_t* q9  = (const uint64_t*)&pc[9][0];
    const uint64_t* q10 = (const uint64_t*)&pc[10][0];
    const uint64_t* q11 = (const uint64_t*)&pc[11][0];
    const uint64_t* q12 = (const uint64_t*)&pc[12][0];
    const uint64_t* q13 = (const uint64_t*)&pc[13][0];
    const uint64_t* q14 = (const uint64_t*)&pc[14][0];
    const uint64_t* q15 = (const uint64_t*)&pc[15][0];
    const uint64_t* q16 = (const uint64_t*)&pc[16][0];
    const uint64_t* q17 = (const uint64_t*)&pc[17][0];
    const uint64_t* q18 = (const uint64_t*)&pc[18][0];

    // Two passes of 2 frequencies each: f = tid + 512*pass + 256*j
#pragma unroll 1
    for (int pass = 0; pass < 2; pass++) {
        float zis[2];
        uint64_t yk[2], ny2[2];
#pragma unroll
        for (int j = 0; j < 2; j++) {
            int f = tid + 512 * pass + 256 * j;
            float s, c;
            sincospif((float)f * (1.0f / LL), &s, &c);
            float y = 2.0f * __fdividef(s, c);
            zis[j] = y;
            yk[j]  = pk2(y, y);
            ny2[j] = pk2(-y * y, -y * y);
        }

        uint64_t a00r[2] = {0, 0}, a00i[2] = {0, 0};
        uint64_t a01r[2] = {0, 0}, a01i[2] = {0, 0};
        uint64_t a10r[2] = {0, 0}, a10i[2] = {0, 0};
        uint64_t a11r[2] = {0, 0}, a11i[2] = {0, 0};

#pragma unroll 1
        for (int g = 0; g < NG; g++) {       // packed pair-group (2 pairs/lane)
            // reciprocal of the quadratic denominator for both freqs
            uint64_t sr[2], msi[2], si[2];
            {
                uint64_t Si = q0[g], nSr = q1[g], Pr = q2[g], Pi = q3[g];
#pragma unroll
                for (int j = 0; j < 2; j++) {
                    uint64_t t   = add2(ny2[j], Pr);
                    uint64_t Dr  = fma2(yk[j], Si,  t);
                    uint64_t Di  = fma2(yk[j], nSr, Pi);
                    uint64_t den = fma2(Dr, Dr, mul2(Di, Di));
                    uint64_t inv = rcp2(den);
                    sr[j]  = mul2(Dr, inv);                    //  Re 1/D
                    msi[j] = mul2(Di, inv);                    // -Im 1/D
                    si[j]  = msi[j] ^ 0x8000000080000000ULL;   //  Im 1/D (ALU)
                }
            }
            // kind 00
            {
                uint64_t N0r = q4[g], N0i = q5[g], N1r = q6[g], nN1i = q7[g];
#pragma unroll
                for (int j = 0; j < 2; j++) {
                    uint64_t Nr = fma2(yk[j], nN1i, N0r);
                    uint64_t Ni = fma2(yk[j], N1r,  N0i);
                    a00r[j] = fma2(Nr, sr[j], a00r[j]); a00r[j] = fma2(Ni, msi[j], a00r[j]);
                    a00i[j] = fma2(Nr, si[j], a00i[j]); a00i[j] = fma2(Ni, sr[j],  a00i[j]);
                }
            }
            // kind 01
            {
                uint64_t N0r = q8[g], N0i = q9[g], N1r = q10[g], nN1i = q11[g];
#pragma unroll
                for (int j = 0; j < 2; j++) {
                    uint64_t Nr = fma2(yk[j], nN1i, N0r);
                    uint64_t Ni = fma2(yk[j], N1r,  N0i);
                    a01r[j] = fma2(Nr, sr[j], a01r[j]); a01r[j] = fma2(Ni, msi[j], a01r[j]);
                    a01i[j] = fma2(Nr, si[j], a01i[j]); a01i[j] = fma2(Ni, sr[j],  a01i[j]);
                }
            }
            // kind 10
            {
                uint64_t N0r = q12[g], N0i = q13[g], N1r = q14[g], nN1i = q15[g];
#pragma unroll
                for (int j = 0; j < 2; j++) {
                    uint64_t Nr = fma2(yk[j], nN1i, N0r);
                    uint64_t Ni = fma2(yk[j], N1r,  N0i);
                    a10r[j] = fma2(Nr, sr[j], a10r[j]); a10r[j] = fma2(Ni, msi[j], a10r[j]);
                    a10i[j] = fma2(Nr, si[j], a10i[j]); a10i[j] = fma2(Ni, sr[j],  a10i[j]);
                }
            }
            // kind 11 (N1 real)
            {
                uint64_t N0r = q16[g], N0i = q17[g], N1 = q18[g];
#pragma unroll
                for (int j = 0; j < 2; j++) {
                    uint64_t Ni = fma2(yk[j], N1, N0i);
                    a11r[j] = fma2(N0r, sr[j], a11r[j]); a11r[j] = fma2(Ni, msi[j], a11r[j]);
                    a11i[j] = fma2(N0r, si[j], a11i[j]); a11i[j] = fma2(Ni, sr[j],  a11i[j]);
                }
            }
        }

#pragma unroll
        for (int j = 0; j < 2; j++) {
            int f = tid + 512 * pass + 256 * j;
            woodbury(lanesum(a00r[j]), lanesum(a00i[j]),
                     lanesum(a01r[j]), lanesum(a01i[j]),
                     lanesum(a10r[j]), lanesum(a10i[j]),
                     lanesum(a11r[j]), lanesum(a11i[j]),
                     dt, 0.5f * zis[j], f, Xr, Xi);
        }
    }

    // Nyquist bin f = L/2 (removable singularity): limit = 0.5*dt*sum_n v00r
    if (tid == 0) {
        float sr = 0.f;
        for (int p = 0; p < NP; p++) sr += pc[6][p];   // pair N1r(00) = v00r sums
        Xr[MM] = 0.5f * dt * sr;
        Xi[MM] = 0.f;
    }
    __syncthreads();

    // ---- Phase 2: irfft via 1024-pt complex inverse FFT ----
    const float scl = 1.0f / 2048.0f;
#pragma unroll
    for (int j = 0; j < 4; j++) {
        int k = tid + 256 * j;
        float Xkx = Xr[k],      Xky = Xi[k];
        float Xmx = Xr[MM - k], Xmy = Xi[MM - k];
        if (k == 0) { Xky = 0.f; Xmy = 0.f; }   // drop imag of DC & Nyquist
        float er  = (Xkx + Xmx) * scl;
        float ei  = (Xky - Xmy) * scl;
        float pr  = (Xkx - Xmx) * scl;
        float pi_ = (Xky + Xmy) * scl;
        float s, c;
        sincospif((float)k * (1.0f / MM), &s, &c);  // e^{+i*pi*k/1024}
        float Or = pr * c - pi_ * s;
        float Oi = pr * s + pi_ * c;
        Zc[k] = make_float2(er - Oi, ei + Or);      // Z = E + i*O
    }
    __syncthreads();

    // 10 radix-2 DIF stages executed as 5 fused double-stages.
#pragma unroll
    for (int q = 256; q >= 1; q >>= 2) {
        const int m = tid & (q - 1);
        const int g = ((tid - m) << 2) + m;
        const int t1 = m * (256 / q);

        float2 a = Zc[g], b = Zc[g + q], c = Zc[g + 2 * q], d = Zc[g + 3 * q];

        float2 w1 = tw[t1];
        float2 w2 = tw[t1 + 256];
        float2 t0v = cadd(a, c);
        float2 t1v = cmul(csub(a, c), w1);
        float2 t2v = cadd(b, d);
        float2 t3v = cmul(csub(b, d), w2);

        float2 w3 = tw[m * (512 / q)];
        Zc[g]         = cadd(t0v, t2v);
        Zc[g + q]     = cmul(csub(t0v, t2v), w3);
        Zc[g + 2 * q] = cadd(t1v, t3v);
        Zc[g + 3 * q] = cmul(csub(t1v, t3v), w3);
        __syncthreads();
    }

    float2* out2 = reinterpret_cast<float2*>(out + h * LL);
#pragma unroll
    for (int j = 0; j < 4; j++) {
        int p = tid + 256 * j;
        int n = __brev((unsigned)p) >> 22;   // 10-bit reverse
        out2[n] = Zc[p];
    }
}

extern "C" void kernel_launch(void* const* d_in, const int* in_sizes, int n_in,
                              void* d_out, int out_size) {
    (void)in_sizes; (void)n_in; (void)out_size;
    const float* C  = (const float*)d_in[0];
    const float* B  = (const float*)d_in[1];
    const float* P  = (const float*)d_in[2];
    const float* W  = (const float*)d_in[3];
    const float* ld = (const float*)d_in[4];
    fused_kernel<<<HH, TPB>>>(C, B, P, W, ld, (float*)d_out);
}

// round 13
// speedup vs baseline: 1.4677x; 1.0151x over previous
#include <cuda_runtime.h>
#include <math.h>
#include <stdint.h>

#define HH   256
#define NN   64
#define NP   32      // n-pairs
#define NG   16      // packed pair-groups (2 pairs per f32x2)
#define LL   2048
#define FF   1025
#define MM   1024
#define TPB  512

// ---- f32x2 packed helpers (Blackwell) ----
__device__ __forceinline__ uint64_t pk2(float lo, float hi) {
    uint64_t r; asm("mov.b64 %0,{%1,%2};" : "=l"(r) : "f"(lo), "f"(hi)); return r;
}
__device__ __forceinline__ void up2(uint64_t v, float& lo, float& hi) {
    asm("mov.b64 {%0,%1},%2;" : "=f"(lo), "=f"(hi) : "l"(v));
}
__device__ __forceinline__ uint64_t add2(uint64_t a, uint64_t b) {
    uint64_t d; asm("add.rn.f32x2 %0,%1,%2;" : "=l"(d) : "l"(a), "l"(b)); return d;
}
__device__ __forceinline__ uint64_t mul2(uint64_t a, uint64_t b) {
    uint64_t d; asm("mul.rn.f32x2 %0,%1,%2;" : "=l"(d) : "l"(a), "l"(b)); return d;
}
__device__ __forceinline__ uint64_t fma2(uint64_t a, uint64_t b, uint64_t c) {
    uint64_t d; asm("fma.rn.f32x2 %0,%1,%2,%3;" : "=l"(d) : "l"(a), "l"(b), "l"(c)); return d;
}
__device__ __forceinline__ uint64_t rcp2(uint64_t v) {
    float lo, hi; up2(v, lo, hi);
    float a, b;
    asm("rcp.approx.f32 %0,%1;" : "=f"(a) : "f"(lo));
    asm("rcp.approx.f32 %0,%1;" : "=f"(b) : "f"(hi));
    return pk2(a, b);
}
__device__ __forceinline__ float lanesum(uint64_t v) {
    float lo, hi; up2(v, lo, hi); return lo + hi;
}

// complex helpers on float2
__device__ __forceinline__ float2 cadd(float2 a, float2 b) { return make_float2(a.x + b.x, a.y + b.y); }
__device__ __forceinline__ float2 csub(float2 a, float2 b) { return make_float2(a.x - b.x, a.y - b.y); }
__device__ __forceinline__ float2 cmul(float2 a, float2 w) {
    return make_float2(a.x * w.x - a.y * w.y, a.x * w.y + a.y * w.x);
}

// Woodbury + bilinear gain epilogue for one frequency -> X in smem
__device__ __forceinline__ void woodbury(float A00r, float A00i, float A01r, float A01i,
                                         float A10r, float A10i, float A11r, float A11i,
                                         float dt, float gi, int f,
                                         float* __restrict__ Xr, float* __restrict__ Xi) {
    float r00r = dt * A00r, r00i = dt * A00i;
    float r01r = dt * A01r, r01i = dt * A01i;
    float r10r = dt * A10r, r10i = dt * A10i;
    float r11r = dt * A11r, r11i = dt * A11i;
    float numr = r01r * r10r - r01i * r10i;
    float numi = r01r * r10i + r01i * r10r;
    float denr = 1.0f + r11r;
    float deni = r11i;
    float dd   = denr * denr + deni * deni;
    float dinv; asm("rcp.approx.f32 %0,%1;" : "=f"(dinv) : "f"(dd));
    float qr = (numr * denr + numi * deni) * dinv;
    float qi = (numi * denr - numr * deni) * dinv;
    float xr = r00r - qr;
    float xi = r00i - qi;
    Xr[f] = xr - xi * gi;      // * (1 + i*gi), gi = tan(pi f / L)
    Xi[f] = xr * gi + xi;
}

// ---------------------------------------------------------------------------
// Fused kernel, one block per h, 512 threads, target 2 blocks/SM (32 warps).
// Phase 1: Cauchy via common-denominator pole pairs, TWO PASSES of ONE freq
//   each (16 packed accumulator regs; lean live set to fit the 64-reg cap).
// Phase 2: irfft(L=2048) via 1024-pt inverse FFT, radix-4 composed stages
//   (256 active threads; others idle through 5 barriers).
// ---------------------------------------------------------------------------
__global__ __launch_bounds__(TPB, 2)
void fused_kernel(const float* __restrict__ Cin, const float* __restrict__ Bin,
                  const float* __restrict__ Pin, const float* __restrict__ Win,
                  const float* __restrict__ logdt, float* __restrict__ out) {
    // raw per-n values (setup scratch)
    __shared__ __align__(16) float raw[9][NN];   // 0 wr,1 wi,2 v00r,3 v00i,4 v01r,5 v01i,6 v10r,7 v10i,8 v11r
    // per-pair constants:
    // 0 S_i, 1 -S_r, 2 P_r, 3 P_i,
    // 4..7   A00: N0r, N0i, N1r, -N1i
    // 8..11  A01: N0r, N0i, N1r, -N1i
    // 12..15 A10: N0r, N0i, N1r, -N1i
    // 16..18 A11: N0r, N0i, N1 (real)
    __shared__ __align__(16) float pc[19][NP];
    __shared__ float2 tw[MM / 2];                // e^{+2*pi*i*t/1024}
    __shared__ float Xr[FF + 3], Xi[FF + 3];
    __shared__ float2 Zc[MM];

    const int h   = blockIdx.x;
    const int tid = threadIdx.x;
    const float dt = expf(logdt[h]);

    // twiddle table: one entry per thread
    {
        float s, c;
        sincospif((float)tid * (1.0f / 512.0f), &s, &c);
        tw[tid] = make_float2(c, s);
    }

    if (tid < NN) {
        const int base = h * (NN * 2) + tid * 2;
        float cr = Cin[base], ci = Cin[base + 1];
        float br = Bin[base], bi = Bin[base + 1];
        float pr = Pin[base], pi = Pin[base + 1];
        float wr = Win[base], wi = Win[base + 1];
        raw[0][tid] = wr * dt;             // w_dt
        raw[1][tid] = wi * dt;
        raw[2][tid] = br * cr - bi * ci;   // v00 = B*C
        raw[3][tid] = br * ci + bi * cr;
        raw[4][tid] = br * pr + bi * pi;   // v01 = B*conj(P)
        raw[5][tid] = bi * pr - br * pi;
        raw[6][tid] = pr * cr - pi * ci;   // v10 = P*C
        raw[7][tid] = pr * ci + pi * cr;
        raw[8][tid] = pr * pr + pi * pi;   // v11 = |P|^2 (real)
    }
    __syncthreads();

    if (tid < NP) {
        const int n0 = 2 * tid, n1 = 2 * tid + 1;
        float wr0 = raw[0][n0], wi0 = raw[1][n0];
        float wr1 = raw[0][n1], wi1 = raw[1][n1];
        pc[0][tid] = wi0 + wi1;                      //  S_i
        pc[1][tid] = -(wr0 + wr1);                   // -S_r
        pc[2][tid] = wr0 * wr1 - wi0 * wi1;          //  P_r
        pc[3][tid] = wr0 * wi1 + wi0 * wr1;          //  P_i
#pragma unroll
        for (int k = 0; k < 3; k++) {
            float ar0 = raw[2 + 2 * k][n0], ai0 = raw[3 + 2 * k][n0];
            float ar1 = raw[2 + 2 * k][n1], ai1 = raw[3 + 2 * k][n1];
            // N0 = -(a0*w1 + a1*w0), N1 = a0 + a1
            pc[4 + 4 * k][tid] = -(ar0 * wr1 - ai0 * wi1 + ar1 * wr0 - ai1 * wi0);
            pc[5 + 4 * k][tid] = -(ar0 * wi1 + ai0 * wr1 + ar1 * wi0 + ai1 * wr0);
            pc[6 + 4 * k][tid] = ar0 + ar1;
            pc[7 + 4 * k][tid] = -(ai0 + ai1);
        }
        {   // A11: a real
            float a0 = raw[8][n0], a1 = raw[8][n1];
            pc[16][tid] = -(a0 * wr1 + a1 * wr0);    // N0r
            pc[17][tid] = -(a0 * wi1 + a1 * wi0);    // N0i
            pc[18][tid] = a0 + a1;                   // N1 (real)
        }
    }
    __syncthreads();

    const uint64_t* qb = (const uint64_t*)&pc[0][0];   // row stride NG u64s

    // Two passes of ONE frequency each: f = tid + 512*pass
#pragma unroll 1
    for (int pass = 0; pass < 2; pass++) {
        const int f = tid + 512 * pass;
        float y;
        {
            float s, c;
            sincospif((float)f * (1.0f / LL), &s, &c);
            y = 2.0f * __fdividef(s, c);
        }
        const uint64_t yk  = pk2(y, y);
        const uint64_t ny2 = pk2(-y * y, -y * y);

        uint64_t a00r = 0, a00i = 0, a01r = 0, a01i = 0;
        uint64_t a10r = 0, a10i = 0, a11r = 0, a11i = 0;

#pragma unroll 1
        for (int g = 0; g < NG; g++) {       // packed pair-group (2 pairs/lane)
            const uint64_t* q = qb + g;
            uint64_t sr, msi, si;
            {
                uint64_t Dr  = fma2(yk, q[0 * NG], add2(ny2, q[2 * NG]));
                uint64_t Di  = fma2(yk, q[1 * NG], q[3 * NG]);
                uint64_t den = fma2(Dr, Dr, mul2(Di, Di));
                uint64_t inv = rcp2(den);
                sr  = mul2(Dr, inv);                    //  Re 1/D
                msi = mul2(Di, inv);                    // -Im 1/D
                si  = msi ^ 0x8000000080000000ULL;      //  Im 1/D (ALU)
            }
            // kind 00
            {
                uint64_t Nr = fma2(yk, q[7 * NG], q[4 * NG]);
                uint64_t Ni = fma2(yk, q[6 * NG], q[5 * NG]);
                a00r = fma2(Nr, sr, a00r); a00r = fma2(Ni, msi, a00r);
                a00i = fma2(Nr, si, a00i); a00i = fma2(Ni, sr,  a00i);
            }
            // kind 01
            {
                uint64_t Nr = fma2(yk, q[11 * NG], q[8 * NG]);
                uint64_t Ni = fma2(yk, q[10 * NG], q[9 * NG]);
                a01r = fma2(Nr, sr, a01r); a01r = fma2(Ni, msi, a01r);
                a01i = fma2(Nr, si, a01i); a01i = fma2(Ni, sr,  a01i);
            }
            // kind 10
            {
                uint64_t Nr = fma2(yk, q[15 * NG], q[12 * NG]);
                uint64_t Ni = fma2(yk, q[14 * NG], q[13 * NG]);
                a10r = fma2(Nr, sr, a10r); a10r = fma2(Ni, msi, a10r);
                a10i = fma2(Nr, si, a10i); a10i = fma2(Ni, sr,  a10i);
            }
            // kind 11 (N1 real)
            {
                uint64_t Nr = q[16 * NG];
                uint64_t Ni = fma2(yk, q[18 * NG], q[17 * NG]);
                a11r = fma2(Nr, sr, a11r); a11r = fma2(Ni, msi, a11r);
                a11i = fma2(Nr, si, a11i); a11i = fma2(Ni, sr,  a11i);
            }
        }

        woodbury(lanesum(a00r), lanesum(a00i),
                 lanesum(a01r), lanesum(a01i),
                 lanesum(a10r), lanesum(a10i),
                 lanesum(a11r), lanesum(a11i),
                 dt, 0.5f * y, f, Xr, Xi);
    }

    // Nyquist bin f = L/2 (removable singularity): limit = 0.5*dt*sum_n v00r
    if (tid == 0) {
        float sr = 0.f;
        for (int p = 0; p < NP; p++) sr += pc[6][p];   // pair N1r(00) = v00r sums
        Xr[MM] = 0.5f * dt * sr;
        Xi[MM] = 0.f;
    }
    __syncthreads();

    // ---- Phase 2: irfft via 1024-pt complex inverse FFT ----
    const float scl = 1.0f / 2048.0f;
#pragma unroll
    for (int j = 0; j < 2; j++) {
        int k = tid + 512 * j;
        float Xkx = Xr[k],      Xky = Xi[k];
        float Xmx = Xr[MM - k], Xmy = Xi[MM - k];
        if (k == 0) { Xky = 0.f; Xmy = 0.f; }   // drop imag of DC & Nyquist
        float er  = (Xkx + Xmx) * scl;
        float ei  = (Xky - Xmy) * scl;
        float pr  = (Xkx - Xmx) * scl;
        float pi_ = (Xky + Xmy) * scl;
        float s, c;
        sincospif((float)k * (1.0f / MM), &s, &c);  // e^{+i*pi*k/1024}
        float Or = pr * c - pi_ * s;
        float Oi = pr * s + pi_ * c;
        Zc[k] = make_float2(er - Oi, ei + Or);      // Z = E + i*O
    }
    __syncthreads();

    // 10 radix-2 DIF stages as 5 fused double-stages; 256 active threads.
#pragma unroll
    for (int q = 256; q >= 1; q >>= 2) {
        if (tid < 256) {
            const int m = tid & (q - 1);
            const int g = ((tid - m) << 2) + m;
            const int t1 = m * (256 / q);

            float2 a = Zc[g], b = Zc[g + q], c = Zc[g + 2 * q], d = Zc[g + 3 * q];

            float2 w1 = tw[t1];
            float2 w2 = tw[t1 + 256];
            float2 t0v = cadd(a, c);
            float2 t1v = cmul(csub(a, c), w1);
            float2 t2v = cadd(b, d);
            float2 t3v = cmul(csub(b, d), w2);

            float2 w3 = tw[m * (512 / q)];
            Zc[g]         = cadd(t0v, t2v);
            Zc[g + q]     = cmul(csub(t0v, t2v), w3);
            Zc[g + 2 * q] = cadd(t1v, t3v);
            Zc[g + 3 * q] = cmul(csub(t1v, t3v), w3);
        }
        __syncthreads();
    }

    float2* out2 = reinterpret_cast<float2*>(out + h * LL);
#pragma unroll
    for (int j = 0; j < 2; j++) {
        int p = tid + 512 * j;
        int n = __brev((unsigned)p) >> 22;   // 10-bit reverse
        out2[n] = Zc[p];
    }
}

extern "C" void kernel_launch(void* const* d_in, const int* in_sizes, int n_in,
                              void* d_out, int out_size) {
    (void)in_sizes; (void)n_in; (void)out_size;
    const float* C  = (const float*)d_in[0];
    const float* B  = (const float*)d_in[1];
    const float* P  = (const float*)d_in[2];
    const float* W  = (const float*)d_in[3];
    const float* ld = (const float*)d_in[4];
    fused_kernel<<<HH, TPB>>>(C, B, P, W, ld, (float*)d_out);
}